// round 12
// baseline (speedup 1.0000x reference)
#include <cuda_runtime.h>
#include <cuda_bf16.h>
#include <mma.h>
#include <math.h>
#include <stdint.h>

using namespace nvcuda;

#define Nn 8192
#define Dd 512
#define Cc 100

__device__ __forceinline__ uint32_t smem_u32(const void* p) {
    uint32_t a;
    asm("{ .reg .u64 t; cvta.to.shared.u64 t, %1; cvt.u32.u64 %0, t; }" : "=r"(a) : "l"(p));
    return a;
}
__device__ __forceinline__ void cp16(void* sdst, const void* gsrc) {
    uint32_t s = smem_u32(sdst);
    asm volatile("cp.async.cg.shared.global [%0], [%1], 16;" :: "r"(s), "l"(gsrc));
}
#define CP_COMMIT()  asm volatile("cp.async.commit_group;" ::: "memory")
#define CP_WAIT(n)   asm volatile("cp.async.wait_group %0;" :: "n"(n) : "memory")

// ---- scratch (static device memory; no allocations) ----
__device__ float g_s[Nn];
__device__ float g_w[Nn];
__device__ int   g_cls[Nn];
__device__ float g_G[Dd * Dd];
__device__ __nv_bfloat16 g_yhi[Dd * Nn];   // yT hi plane [512][8192]
__device__ __nv_bfloat16 g_ylo[Dd * Nn];   // yT lo plane
#define NTRI2 10
#define SPLITK 14
__device__ float g_part[SPLITK * NTRI2 * 128 * 128];
// scatter partials: fully overwritten each run -> no zeroing needed
#define RSPLIT 8
__device__ float g_Ap[RSPLIT * Cc * Dd];
__device__ float g_Bp[RSPLIT * Cc * Dd];
__device__ float g_cntp[RSPLIT * Cc];

// ---------------- per-row stats ----------------
__global__ void k_rowstats(const float* __restrict__ x,
                           const float* __restrict__ logits) {
    int row = blockIdx.x;
    int t = threadIdx.x;            // 128 threads
    __shared__ float red[128];
    __shared__ int   redi[128];

    const float* xr = x + (size_t)row * Dd;
    float s2 = 0.f;
    #pragma unroll
    for (int i = t; i < Dd; i += 128) { float v = xr[i]; s2 += v * v; }
    red[t] = s2; __syncthreads();
    for (int o = 64; o > 0; o >>= 1) { if (t < o) red[t] += red[t + o]; __syncthreads(); }
    float norm2 = red[0];
    __syncthreads();

    const float* lr = logits + (size_t)row * Cc;
    float lv = (t < Cc) ? lr[t] : -3.402823466e38f;
    red[t] = lv; redi[t] = t; __syncthreads();
    for (int o = 64; o > 0; o >>= 1) {
        if (t < o) {
            float ov = red[t + o]; int oi = redi[t + o];
            if (ov > red[t] || (ov == red[t] && oi < redi[t])) { red[t] = ov; redi[t] = oi; }
        }
        __syncthreads();
    }
    float lmax = red[0];
    int cls = redi[0];
    __syncthreads();

    float e = (t < Cc) ? expf(lv - lmax) : 0.f;
    red[t] = e; __syncthreads();
    for (int o = 64; o > 0; o >>= 1) { if (t < o) red[t] += red[t + o]; __syncthreads(); }
    if (t == 0) {
        g_s[row]   = 1.f / fmaxf(sqrtf(norm2), 1e-8f);
        g_w[row]   = 1.f / red[0];
        g_cls[row] = cls;
    }
}

// ---------------- transpose + bf16 hi/lo split of y = sqrt(s)*x ----------------
__global__ void k_split(const float* __restrict__ x) {
    __shared__ float sm[32][33];
    int d0 = blockIdx.x * 32, n0 = blockIdx.y * 32;
    int tx = threadIdx.x & 31, ty = threadIdx.x >> 5;   // 32x8
    #pragma unroll
    for (int i = ty; i < 32; i += 8) {
        float sq = sqrtf(g_s[n0 + i]);
        sm[i][tx] = x[(size_t)(n0 + i) * Dd + d0 + tx] * sq;
    }
    __syncthreads();
    #pragma unroll
    for (int r = ty; r < 32; r += 8) {
        float v = sm[tx][r];                        // y[n0+tx][d0+r]
        __nv_bfloat16 hi = __float2bfloat16(v);
        float lo = v - __bfloat162float(hi);
        g_yhi[(size_t)(d0 + r) * Nn + n0 + tx] = hi;
        g_ylo[(size_t)(d0 + r) * Nn + n0 + tx] = __float2bfloat16(lo);
    }
}

// ---------------- G = Y^T Y via WMMA, cp.async 3-stage pipeline ----------------
#define KC 64
#define KCHUNKS (Nn / KC)       // 128 chunks, split nonuniformly over SPLITK
#define PITCH 72                // bf16/row: 144B stride = 9*16B (ldmatrix-aligned)
#define TILE_E (128 * PITCH)    // elems per plane
#define STAGE_E (4 * TILE_E)    // Ah,Al,Bh,Bl
#define NSTAGE 3
#define GRAM_SMEM (NSTAGE * STAGE_E * 2)   // 221184 bytes

__device__ __forceinline__ void fill_plane_async(__nv_bfloat16* sm,
                                                 const __nv_bfloat16* plane,
                                                 int row0, int k0, int tid) {
    #pragma unroll
    for (int p = 0; p < 4; p++) {
        int idx = p * 256 + tid;     // 0..1023 : 128 rows x 8 chunks of 16B
        int row = idx >> 3;
        int q   = idx & 7;
        cp16(sm + row * PITCH + q * 8,
             plane + (size_t)(row0 + row) * Nn + k0 + q * 8);
    }
}

__device__ __forceinline__ void fill_stage(__nv_bfloat16* base, int a0, int b0,
                                           bool diag, int k0, int tid) {
    fill_plane_async(base,              g_yhi, a0, k0, tid);
    fill_plane_async(base + TILE_E,     g_ylo, a0, k0, tid);
    if (!diag) {
        fill_plane_async(base + 2 * TILE_E, g_yhi, b0, k0, tid);
        fill_plane_async(base + 3 * TILE_E, g_ylo, b0, k0, tid);
    }
    CP_COMMIT();
}

__global__ void __launch_bounds__(256) k_gram_wmma() {
    extern __shared__ __nv_bfloat16 smem[];

    int tid = threadIdx.x;
    int wid = tid >> 5;
    int wm = wid & 3;       // 4 warps in M (32 rows each)
    int wn = wid >> 2;      // 2 warps in N (64 cols each)

    // decode upper-tri tile index (4x4 tiles of 128)
    int t = blockIdx.x, ti = 0, rem = t;
    while (rem >= 4 - ti) { rem -= 4 - ti; ti++; }
    int tj = ti + rem;
    int a0 = ti * 128, b0 = tj * 128;
    bool diag = (ti == tj);

    int split = blockIdx.y;
    int cstart = (split * KCHUNKS) / SPLITK;
    int cend   = ((split + 1) * KCHUNKS) / SPLITK;
    int nst = cend - cstart;

    wmma::fragment<wmma::accumulator, 16, 16, 16, float> acc[2][4];
    #pragma unroll
    for (int i = 0; i < 2; i++)
        #pragma unroll
        for (int j = 0; j < 4; j++)
            wmma::fill_fragment(acc[i][j], 0.f);

    // prefetch stages 0 and 1
    fill_stage(smem,           a0, b0, diag, cstart * KC, tid);
    fill_stage(smem + STAGE_E, a0, b0, diag, (cstart + 1) * KC, tid);

    for (int st = 0; st < nst; st++) {
        // wait for stage st (two groups may be in flight behind it)
        if (st + 1 < nst) { CP_WAIT(1); } else { CP_WAIT(0); }
        __syncthreads();

        // refill the buffer consumed at st-1 with stage st+2
        if (st + 2 < nst)
            fill_stage(smem + ((st + 2) % NSTAGE) * STAGE_E, a0, b0, diag,
                       (cstart + st + 2) * KC, tid);

        __nv_bfloat16* Ah = smem + (st % NSTAGE) * STAGE_E;
        __nv_bfloat16* Al = Ah + TILE_E;
        const __nv_bfloat16* bh = diag ? Ah : (Ah + 2 * TILE_E);
        const __nv_bfloat16* bl = diag ? Al : (Ah + 3 * TILE_E);

        #pragma unroll
        for (int kk = 0; kk < KC / 16; kk++) {
            wmma::fragment<wmma::matrix_a, 16, 16, 16, __nv_bfloat16, wmma::row_major> ah[2], al[2];
            wmma::fragment<wmma::matrix_b, 16, 16, 16, __nv_bfloat16, wmma::col_major> fh[4], fl[4];
            #pragma unroll
            for (int i = 0; i < 2; i++) {
                int r = wm * 32 + i * 16;
                wmma::load_matrix_sync(ah[i], Ah + r * PITCH + kk * 16, PITCH);
                wmma::load_matrix_sync(al[i], Al + r * PITCH + kk * 16, PITCH);
            }
            #pragma unroll
            for (int j = 0; j < 4; j++) {
                int c = wn * 64 + j * 16;
                wmma::load_matrix_sync(fh[j], bh + c * PITCH + kk * 16, PITCH);
                wmma::load_matrix_sync(fl[j], bl + c * PITCH + kk * 16, PITCH);
            }
            #pragma unroll
            for (int i = 0; i < 2; i++)
                #pragma unroll
                for (int j = 0; j < 4; j++) {
                    wmma::mma_sync(acc[i][j], ah[i], fh[j], acc[i][j]);
                    wmma::mma_sync(acc[i][j], ah[i], fl[j], acc[i][j]);
                    wmma::mma_sync(acc[i][j], al[i], fh[j], acc[i][j]);
                }
        }
    }

    float* dst = g_part + ((size_t)split * NTRI2 + blockIdx.x) * 16384;
    #pragma unroll
    for (int i = 0; i < 2; i++)
        #pragma unroll
        for (int j = 0; j < 4; j++)
            wmma::store_matrix_sync(dst + (wm * 32 + i * 16) * 128 + wn * 64 + j * 16,
                                    acc[i][j], 128, wmma::mem_row_major);
}

// ---------------- reduce splits -> G (+ mirror lower triangle) ----------------
__global__ void k_reduce() {
    int tile = blockIdx.y;
    int ti = 0, rem = tile;
    while (rem >= 4 - ti) { rem -= 4 - ti; ti++; }
    int tj = ti + rem;

    int i = blockIdx.x * blockDim.x + threadIdx.x;   // 0..4095 (float4 index)
    int row = i >> 5;
    int c4  = (i & 31) * 4;
    float4 acc = make_float4(0.f, 0.f, 0.f, 0.f);
    #pragma unroll
    for (int s = 0; s < SPLITK; s++) {
        float4 v = *(const float4*)(g_part + ((size_t)s * NTRI2 + tile) * 16384 + row * 128 + c4);
        acc.x += v.x; acc.y += v.y; acc.z += v.z; acc.w += v.w;
    }
    int a = ti * 128 + row, b = tj * 128 + c4;
    *(float4*)(g_G + (size_t)a * Dd + b) = acc;
    if (ti != tj) {
        g_G[(size_t)(b + 0) * Dd + a] = acc.x;
        g_G[(size_t)(b + 1) * Dd + a] = acc.y;
        g_G[(size_t)(b + 2) * Dd + a] = acc.z;
        g_G[(size_t)(b + 3) * Dd + a] = acc.w;
    }
}

// ---------------- per-class weighted partials (no pre-zero needed) ----------------
__global__ void k_scatter(const float* __restrict__ x) {
    __shared__ float sA[Cc][32];
    __shared__ float sB[Cc][32];
    __shared__ float sC[Cc];
    int c0 = blockIdx.x * 32;
    int split = blockIdx.y;
    int r0 = split * (Nn / RSPLIT);
    int tid = threadIdx.x;
    int tx = tid & 31, ty = tid >> 5;

    for (int i = tid; i < Cc * 32; i += 256) { (&sA[0][0])[i] = 0.f; (&sB[0][0])[i] = 0.f; }
    for (int i = tid; i < Cc; i += 256) sC[i] = 0.f;
    __syncthreads();

    int rend = r0 + (Nn / RSPLIT);
    for (int r = r0 + ty; r < rend; r += 8) {
        int   c  = g_cls[r];
        float w  = g_w[r];
        float ws = w * g_s[r];
        float xv = x[(size_t)r * Dd + c0 + tx];
        atomicAdd(&sA[c][tx], ws * xv);
        atomicAdd(&sB[c][tx], w  * xv);
        if (blockIdx.x == 0 && tx == 0) atomicAdd(&sC[c], 1.f);
    }
    __syncthreads();

    // deterministic overwrite of this block's partial slots
    for (int i = tid; i < Cc * 32; i += 256) {
        int cl = i >> 5, col = i & 31;
        g_Ap[((size_t)split * Cc + cl) * Dd + c0 + col] = sA[cl][col];
        g_Bp[((size_t)split * Cc + cl) * Dd + c0 + col] = sB[cl][col];
    }
    if (blockIdx.x == 0)
        for (int i = tid; i < Cc; i += 256)
            g_cntp[split * Cc + i] = sC[i];
}

// ---------------- prototypes = (A @ G + B) / counts ----------------
__global__ void k_proto(float* __restrict__ out) {
    int c = blockIdx.x;
    int half = blockIdx.y;          // 0 or 1
    int tid = threadIdx.x;          // 256
    int d = half * 256 + tid;
    __shared__ float sA[Dd];

    for (int i = tid; i < Dd; i += 256) {
        float a = 0.f;
        #pragma unroll
        for (int r = 0; r < RSPLIT; r++)
            a += g_Ap[((size_t)r * Cc + c) * Dd + i];
        sA[i] = a;
    }
    __syncthreads();

    float b = 0.f, cnt = 0.f;
    #pragma unroll
    for (int r = 0; r < RSPLIT; r++) {
        b   += g_Bp[((size_t)r * Cc + c) * Dd + d];
        cnt += g_cntp[r * Cc + c];
    }

    float acc = 0.f;
    #pragma unroll 8
    for (int k = 0; k < Dd; k++)
        acc += sA[k] * g_G[(size_t)k * Dd + d];

    float inv = 1.f / fmaxf(cnt, 1.f);
    out[(size_t)c * Dd + d] = (cnt > 0.f) ? (acc + b) * inv : 0.f;
}

// ---------------- inter_class_matrix[i,j,:] = P[j] - P[i] ----------------
__global__ void k_inter(const float* __restrict__ P, float* __restrict__ out) {
    const int D4 = Dd / 4;
    long total = (long)Cc * Cc * D4;
    long stride = (long)gridDim.x * blockDim.x;
    for (long t = (long)blockIdx.x * blockDim.x + threadIdx.x; t < total; t += stride) {
        int d4 = (int)(t % D4);
        long ij = t / D4;
        int j = (int)(ij % Cc);
        int i = (int)(ij / Cc);
        float4 pj = *(const float4*)(P + (size_t)j * Dd + d4 * 4);
        float4 pi = *(const float4*)(P + (size_t)i * Dd + d4 * 4);
        float4 o;
        o.x = pj.x - pi.x; o.y = pj.y - pi.y;
        o.z = pj.z - pi.z; o.w = pj.w - pi.w;
        ((float4*)out)[t] = o;
    }
}

extern "C" void kernel_launch(void* const* d_in, const int* in_sizes, int n_in,
                              void* d_out, int out_size) {
    const float* x      = (const float*)d_in[0];   // [8192, 512]
    const float* logits = (const float*)d_in[1];   // [8192, 100]
    float* out = (float*)d_out;

    cudaFuncSetAttribute(k_gram_wmma, cudaFuncAttributeMaxDynamicSharedMemorySize, GRAM_SMEM);

    k_rowstats<<<Nn, 128>>>(x, logits);
    k_split<<<dim3(Dd / 32, Nn / 32), 256>>>(x);
    k_gram_wmma<<<dim3(NTRI2, SPLITK), 256, GRAM_SMEM>>>();
    k_reduce<<<dim3(16, NTRI2), 256>>>();
    k_scatter<<<dim3(Dd / 32, RSPLIT), 256>>>(x);
    k_proto<<<dim3(Cc, 2), 256>>>(out);
    k_inter<<<2560, 256>>>(out, out + (size_t)Cc * Dd);
}

// round 13
// speedup vs baseline: 1.0667x; 1.0667x over previous
#include <cuda_runtime.h>
#include <cuda_bf16.h>
#include <mma.h>
#include <math.h>
#include <stdint.h>

using namespace nvcuda;

#define Nn 8192
#define Dd 512
#define Cc 100

__device__ __forceinline__ uint32_t smem_u32(const void* p) {
    uint32_t a;
    asm("{ .reg .u64 t; cvta.to.shared.u64 t, %1; cvt.u32.u64 %0, t; }" : "=r"(a) : "l"(p));
    return a;
}
__device__ __forceinline__ void cp16(void* sdst, const void* gsrc) {
    uint32_t s = smem_u32(sdst);
    asm volatile("cp.async.cg.shared.global [%0], [%1], 16;" :: "r"(s), "l"(gsrc));
}
#define CP_COMMIT()  asm volatile("cp.async.commit_group;" ::: "memory")
#define CP_WAIT(n)   asm volatile("cp.async.wait_group %0;" :: "n"(n) : "memory")

// ---- scratch (static device memory; no allocations) ----
__device__ float g_s[Nn];
__device__ float g_w[Nn];
__device__ int   g_cls[Nn];
__device__ float g_G[Dd * Dd];
__device__ __nv_bfloat16 g_yhi[Dd * Nn];   // yT hi plane [512][8192]
__device__ __nv_bfloat16 g_ylo[Dd * Nn];   // yT lo plane
#define NTRI2 10
#define SPLITK 14
__device__ float g_part[SPLITK * NTRI2 * 128 * 128];
// scatter partials: fully overwritten each run -> no zeroing needed
#define RSPLIT 8
__device__ float g_Ap[RSPLIT * Cc * Dd];
__device__ float g_Bp[RSPLIT * Cc * Dd];
__device__ float g_cntp[RSPLIT * Cc];

// ---------------- per-row stats: one warp per row, shfl reductions ----------------
__global__ void k_rowstats(const float* __restrict__ x,
                           const float* __restrict__ logits) {
    int warp = threadIdx.x >> 5;           // 8 warps
    int lane = threadIdx.x & 31;
    int row = blockIdx.x * 8 + warp;

    // ||x_row||^2 : each lane 4 float4
    const float4* xr = (const float4*)(x + (size_t)row * Dd);
    float s2 = 0.f;
    #pragma unroll
    for (int i = 0; i < 4; i++) {
        float4 v = xr[lane + i * 32];
        s2 += v.x * v.x + v.y * v.y + v.z * v.z + v.w * v.w;
    }
    #pragma unroll
    for (int o = 16; o > 0; o >>= 1)
        s2 += __shfl_xor_sync(0xFFFFFFFFu, s2, o);

    // logits: max + first-index argmax over 100, 4 strided entries per lane
    const float* lr = logits + (size_t)row * Cc;
    float lv[4];
    float mv = -3.402823466e38f; int mi = 0x7FFFFFFF;
    #pragma unroll
    for (int k = 0; k < 4; k++) {
        int idx = lane + k * 32;
        lv[k] = (idx < Cc) ? lr[idx] : -3.402823466e38f;
        if (lv[k] > mv) { mv = lv[k]; mi = idx; }   // ascending idx -> first max kept
    }
    #pragma unroll
    for (int o = 16; o > 0; o >>= 1) {
        float ov = __shfl_xor_sync(0xFFFFFFFFu, mv, o);
        int   oi = __shfl_xor_sync(0xFFFFFFFFu, mi, o);
        if (ov > mv || (ov == mv && oi < mi)) { mv = ov; mi = oi; }
    }

    // sum exp(l - max)
    float se = 0.f;
    #pragma unroll
    for (int k = 0; k < 4; k++)
        if (lane + k * 32 < Cc) se += expf(lv[k] - mv);
    #pragma unroll
    for (int o = 16; o > 0; o >>= 1)
        se += __shfl_xor_sync(0xFFFFFFFFu, se, o);

    if (lane == 0) {
        g_s[row]   = 1.f / fmaxf(sqrtf(s2), 1e-8f);
        g_w[row]   = 1.f / se;
        g_cls[row] = mi;
    }
}

// ---------------- transpose + bf16 hi/lo split of y = sqrt(s)*x ----------------
__global__ void k_split(const float* __restrict__ x) {
    __shared__ float sm[32][33];
    int d0 = blockIdx.x * 32, n0 = blockIdx.y * 32;
    int tx = threadIdx.x & 31, ty = threadIdx.x >> 5;   // 32x8
    #pragma unroll
    for (int i = ty; i < 32; i += 8) {
        float sq = sqrtf(g_s[n0 + i]);
        sm[i][tx] = x[(size_t)(n0 + i) * Dd + d0 + tx] * sq;
    }
    __syncthreads();
    #pragma unroll
    for (int r = ty; r < 32; r += 8) {
        float v = sm[tx][r];                        // y[n0+tx][d0+r]
        __nv_bfloat16 hi = __float2bfloat16(v);
        float lo = v - __bfloat162float(hi);
        g_yhi[(size_t)(d0 + r) * Nn + n0 + tx] = hi;
        g_ylo[(size_t)(d0 + r) * Nn + n0 + tx] = __float2bfloat16(lo);
    }
}

// ---------------- G = Y^T Y via WMMA, cp.async 2-stage pipeline ----------------
#define KC 64
#define KCHUNKS (Nn / KC)       // 128 chunks, split nonuniformly over SPLITK
#define PITCH 72                // bf16/row: 144B stride = 9*16B (ldmatrix-aligned)
#define TILE_E (128 * PITCH)    // elems per plane
#define STAGE_E (4 * TILE_E)    // Ah,Al,Bh,Bl
#define GRAM_SMEM (2 * STAGE_E * 2)   // 147456 bytes

__device__ __forceinline__ void fill_plane_async(__nv_bfloat16* sm,
                                                 const __nv_bfloat16* plane,
                                                 int row0, int k0, int tid) {
    #pragma unroll
    for (int p = 0; p < 4; p++) {
        int idx = p * 256 + tid;     // 0..1023 : 128 rows x 8 chunks of 16B
        int row = idx >> 3;
        int q   = idx & 7;
        cp16(sm + row * PITCH + q * 8,
             plane + (size_t)(row0 + row) * Nn + k0 + q * 8);
    }
}

__device__ __forceinline__ void fill_stage(__nv_bfloat16* base, int a0, int b0,
                                           bool diag, int k0, int tid) {
    fill_plane_async(base,              g_yhi, a0, k0, tid);
    fill_plane_async(base + TILE_E,     g_ylo, a0, k0, tid);
    if (!diag) {
        fill_plane_async(base + 2 * TILE_E, g_yhi, b0, k0, tid);
        fill_plane_async(base + 3 * TILE_E, g_ylo, b0, k0, tid);
    }
    CP_COMMIT();
}

__global__ void __launch_bounds__(256) k_gram_wmma() {
    extern __shared__ __nv_bfloat16 smem[];

    int tid = threadIdx.x;
    int wid = tid >> 5;
    int wm = wid & 3;       // 4 warps in M (32 rows each)
    int wn = wid >> 2;      // 2 warps in N (64 cols each)

    // decode upper-tri tile index (4x4 tiles of 128)
    int t = blockIdx.x, ti = 0, rem = t;
    while (rem >= 4 - ti) { rem -= 4 - ti; ti++; }
    int tj = ti + rem;
    int a0 = ti * 128, b0 = tj * 128;
    bool diag = (ti == tj);

    int split = blockIdx.y;
    int cstart = (split * KCHUNKS) / SPLITK;
    int cend   = ((split + 1) * KCHUNKS) / SPLITK;
    int nst = cend - cstart;

    wmma::fragment<wmma::accumulator, 16, 16, 16, float> acc[2][4];
    #pragma unroll
    for (int i = 0; i < 2; i++)
        #pragma unroll
        for (int j = 0; j < 4; j++)
            wmma::fill_fragment(acc[i][j], 0.f);

    // prefetch stage 0
    fill_stage(smem, a0, b0, diag, cstart * KC, tid);

    for (int st = 0; st < nst; st++) {
        int cur = st & 1;
        if (st + 1 < nst) {
            fill_stage(smem + (1 - cur) * STAGE_E, a0, b0, diag,
                       (cstart + st + 1) * KC, tid);
            CP_WAIT(1);
        } else {
            CP_WAIT(0);
        }
        __syncthreads();

        __nv_bfloat16* Ah = smem + cur * STAGE_E;
        __nv_bfloat16* Al = Ah + TILE_E;
        const __nv_bfloat16* bh = diag ? Ah : (Ah + 2 * TILE_E);
        const __nv_bfloat16* bl = diag ? Al : (Ah + 3 * TILE_E);

        #pragma unroll
        for (int kk = 0; kk < KC / 16; kk++) {
            wmma::fragment<wmma::matrix_a, 16, 16, 16, __nv_bfloat16, wmma::row_major> ah[2], al[2];
            wmma::fragment<wmma::matrix_b, 16, 16, 16, __nv_bfloat16, wmma::col_major> fh[4], fl[4];
            #pragma unroll
            for (int i = 0; i < 2; i++) {
                int r = wm * 32 + i * 16;
                wmma::load_matrix_sync(ah[i], Ah + r * PITCH + kk * 16, PITCH);
                wmma::load_matrix_sync(al[i], Al + r * PITCH + kk * 16, PITCH);
            }
            #pragma unroll
            for (int j = 0; j < 4; j++) {
                int c = wn * 64 + j * 16;
                wmma::load_matrix_sync(fh[j], bh + c * PITCH + kk * 16, PITCH);
                wmma::load_matrix_sync(fl[j], bl + c * PITCH + kk * 16, PITCH);
            }
            // product-major order: 8 independent accumulators between reuses
            #pragma unroll
            for (int i = 0; i < 2; i++)
                #pragma unroll
                for (int j = 0; j < 4; j++)
                    wmma::mma_sync(acc[i][j], ah[i], fh[j], acc[i][j]);
            #pragma unroll
            for (int i = 0; i < 2; i++)
                #pragma unroll
                for (int j = 0; j < 4; j++)
                    wmma::mma_sync(acc[i][j], ah[i], fl[j], acc[i][j]);
            #pragma unroll
            for (int i = 0; i < 2; i++)
                #pragma unroll
                for (int j = 0; j < 4; j++)
                    wmma::mma_sync(acc[i][j], al[i], fh[j], acc[i][j]);
        }
        __syncthreads();
    }

    float* dst = g_part + ((size_t)split * NTRI2 + blockIdx.x) * 16384;
    #pragma unroll
    for (int i = 0; i < 2; i++)
        #pragma unroll
        for (int j = 0; j < 4; j++)
            wmma::store_matrix_sync(dst + (wm * 32 + i * 16) * 128 + wn * 64 + j * 16,
                                    acc[i][j], 128, wmma::mem_row_major);
}

// ---------------- reduce splits -> G (+ mirror lower triangle) ----------------
__global__ void k_reduce() {
    int tile = blockIdx.y;
    int ti = 0, rem = tile;
    while (rem >= 4 - ti) { rem -= 4 - ti; ti++; }
    int tj = ti + rem;

    int i = blockIdx.x * blockDim.x + threadIdx.x;   // 0..4095 (float4 index)
    int row = i >> 5;
    int c4  = (i & 31) * 4;
    float4 acc = make_float4(0.f, 0.f, 0.f, 0.f);
    #pragma unroll
    for (int s = 0; s < SPLITK; s++) {
        float4 v = *(const float4*)(g_part + ((size_t)s * NTRI2 + tile) * 16384 + row * 128 + c4);
        acc.x += v.x; acc.y += v.y; acc.z += v.z; acc.w += v.w;
    }
    int a = ti * 128 + row, b = tj * 128 + c4;
    *(float4*)(g_G + (size_t)a * Dd + b) = acc;
    if (ti != tj) {
        g_G[(size_t)(b + 0) * Dd + a] = acc.x;
        g_G[(size_t)(b + 1) * Dd + a] = acc.y;
        g_G[(size_t)(b + 2) * Dd + a] = acc.z;
        g_G[(size_t)(b + 3) * Dd + a] = acc.w;
    }
}

// ---------------- per-class weighted partials (no pre-zero needed) ----------------
__global__ void k_scatter(const float* __restrict__ x) {
    __shared__ float sA[Cc][32];
    __shared__ float sB[Cc][32];
    __shared__ float sC[Cc];
    int c0 = blockIdx.x * 32;
    int split = blockIdx.y;
    int r0 = split * (Nn / RSPLIT);
    int tid = threadIdx.x;
    int tx = tid & 31, ty = tid >> 5;

    for (int i = tid; i < Cc * 32; i += 256) { (&sA[0][0])[i] = 0.f; (&sB[0][0])[i] = 0.f; }
    for (int i = tid; i < Cc; i += 256) sC[i] = 0.f;
    __syncthreads();

    int rend = r0 + (Nn / RSPLIT);
    for (int r = r0 + ty; r < rend; r += 8) {
        int   c  = g_cls[r];
        float w  = g_w[r];
        float ws = w * g_s[r];
        float xv = x[(size_t)r * Dd + c0 + tx];
        atomicAdd(&sA[c][tx], ws * xv);
        atomicAdd(&sB[c][tx], w  * xv);
        if (blockIdx.x == 0 && tx == 0) atomicAdd(&sC[c], 1.f);
    }
    __syncthreads();

    // deterministic overwrite of this block's partial slots
    for (int i = tid; i < Cc * 32; i += 256) {
        int cl = i >> 5, col = i & 31;
        g_Ap[((size_t)split * Cc + cl) * Dd + c0 + col] = sA[cl][col];
        g_Bp[((size_t)split * Cc + cl) * Dd + c0 + col] = sB[cl][col];
    }
    if (blockIdx.x == 0)
        for (int i = tid; i < Cc; i += 256)
            g_cntp[split * Cc + i] = sC[i];
}

// ---------------- prototypes = (A @ G + B) / counts ----------------
__global__ void k_proto(float* __restrict__ out) {
    int c = blockIdx.x;
    int half = blockIdx.y;          // 0 or 1
    int tid = threadIdx.x;          // 256
    int d = half * 256 + tid;
    __shared__ float sA[Dd];

    for (int i = tid; i < Dd; i += 256) {
        float a = 0.f;
        #pragma unroll
        for (int r = 0; r < RSPLIT; r++)
            a += g_Ap[((size_t)r * Cc + c) * Dd + i];
        sA[i] = a;
    }
    __syncthreads();

    float b = 0.f, cnt = 0.f;
    #pragma unroll
    for (int r = 0; r < RSPLIT; r++) {
        b   += g_Bp[((size_t)r * Cc + c) * Dd + d];
        cnt += g_cntp[r * Cc + c];
    }

    float acc = 0.f;
    #pragma unroll 8
    for (int k = 0; k < Dd; k++)
        acc += sA[k] * g_G[(size_t)k * Dd + d];

    float inv = 1.f / fmaxf(cnt, 1.f);
    out[(size_t)c * Dd + d] = (cnt > 0.f) ? (acc + b) * inv : 0.f;
}

// ---------------- inter_class_matrix[i,j,:] = P[j] - P[i] ----------------
__global__ void k_inter(const float* __restrict__ P, float* __restrict__ out) {
    const int D4 = Dd / 4;
    long total = (long)Cc * Cc * D4;
    long stride = (long)gridDim.x * blockDim.x;
    for (long t = (long)blockIdx.x * blockDim.x + threadIdx.x; t < total; t += stride) {
        int d4 = (int)(t % D4);
        long ij = t / D4;
        int j = (int)(ij % Cc);
        int i = (int)(ij / Cc);
        float4 pj = *(const float4*)(P + (size_t)j * Dd + d4 * 4);
        float4 pi = *(const float4*)(P + (size_t)i * Dd + d4 * 4);
        float4 o;
        o.x = pj.x - pi.x; o.y = pj.y - pi.y;
        o.z = pj.z - pi.z; o.w = pj.w - pi.w;
        ((float4*)out)[t] = o;
    }
}

extern "C" void kernel_launch(void* const* d_in, const int* in_sizes, int n_in,
                              void* d_out, int out_size) {
    const float* x      = (const float*)d_in[0];   // [8192, 512]
    const float* logits = (const float*)d_in[1];   // [8192, 100]
    float* out = (float*)d_out;

    cudaFuncSetAttribute(k_gram_wmma, cudaFuncAttributeMaxDynamicSharedMemorySize, GRAM_SMEM);

    k_rowstats<<<Nn / 8, 256>>>(x, logits);
    k_split<<<dim3(Dd / 32, Nn / 32), 256>>>(x);
    k_gram_wmma<<<dim3(NTRI2, SPLITK), 256, GRAM_SMEM>>>();
    k_reduce<<<dim3(16, NTRI2), 256>>>();
    k_scatter<<<dim3(Dd / 32, RSPLIT), 256>>>(x);
    k_proto<<<dim3(Cc, 2), 256>>>(out);
    k_inter<<<2560, 256>>>(out, out + (size_t)Cc * Dd);
}

// round 15
// speedup vs baseline: 1.1887x; 1.1144x over previous
#include <cuda_runtime.h>
#include <cuda_bf16.h>
#include <mma.h>
#include <math.h>
#include <stdint.h>

using namespace nvcuda;

#define Nn 8192
#define Dd 512
#define Cc 100

__device__ __forceinline__ uint32_t smem_u32(const void* p) {
    uint32_t a;
    asm("{ .reg .u64 t; cvta.to.shared.u64 t, %1; cvt.u32.u64 %0, t; }" : "=r"(a) : "l"(p));
    return a;
}
__device__ __forceinline__ void cp16(void* sdst, const void* gsrc) {
    uint32_t s = smem_u32(sdst);
    asm volatile("cp.async.cg.shared.global [%0], [%1], 16;" :: "r"(s), "l"(gsrc));
}
#define CP_COMMIT()  asm volatile("cp.async.commit_group;" ::: "memory")
#define CP_WAIT(n)   asm volatile("cp.async.wait_group %0;" :: "n"(n) : "memory")

// ---- scratch (static device memory; no allocations) ----
__device__ float g_s[Nn];
__device__ float g_w[Nn];
__device__ int   g_cls[Nn];
__device__ float g_cnt[Cc];
__device__ float g_G[Dd * Dd];
__device__ float g_A[Cc * Dd];
__device__ float g_B[Cc * Dd];
__device__ __nv_bfloat16 g_yhi[Dd * Nn];   // yT hi plane [512][8192]
__device__ __nv_bfloat16 g_ylo[Dd * Nn];   // yT lo plane
#define NTRI2 10
#define SPLITK 14
__device__ float g_part[SPLITK * NTRI2 * 128 * 128];

// ---------------- zero A/B/cnt ----------------
__global__ void k_zero() {
    int t = blockIdx.x * blockDim.x + threadIdx.x;
    int stride = gridDim.x * blockDim.x;
    for (int i = t; i < Cc * Dd; i += stride) { g_A[i] = 0.f; g_B[i] = 0.f; }
    for (int i = t; i < Cc; i += stride) g_cnt[i] = 0.f;
}

// ---------------- per-row stats: one warp per row, shfl reductions ----------------
__global__ void k_rowstats(const float* __restrict__ x,
                           const float* __restrict__ logits) {
    int warp = threadIdx.x >> 5;           // 8 warps
    int lane = threadIdx.x & 31;
    int row = blockIdx.x * 8 + warp;

    // ||x_row||^2 : each lane 4 float4
    const float4* xr = (const float4*)(x + (size_t)row * Dd);
    float s2 = 0.f;
    #pragma unroll
    for (int i = 0; i < 4; i++) {
        float4 v = xr[lane + i * 32];
        s2 += v.x * v.x + v.y * v.y + v.z * v.z + v.w * v.w;
    }
    #pragma unroll
    for (int o = 16; o > 0; o >>= 1)
        s2 += __shfl_xor_sync(0xFFFFFFFFu, s2, o);

    // logits: max + first-index argmax over 100
    const float* lr = logits + (size_t)row * Cc;
    float lv[4];
    float mv = -3.402823466e38f; int mi = 0x7FFFFFFF;
    #pragma unroll
    for (int k = 0; k < 4; k++) {
        int idx = lane + k * 32;
        lv[k] = (idx < Cc) ? lr[idx] : -3.402823466e38f;
        if (lv[k] > mv) { mv = lv[k]; mi = idx; }
    }
    #pragma unroll
    for (int o = 16; o > 0; o >>= 1) {
        float ov = __shfl_xor_sync(0xFFFFFFFFu, mv, o);
        int   oi = __shfl_xor_sync(0xFFFFFFFFu, mi, o);
        if (ov > mv || (ov == mv && oi < mi)) { mv = ov; mi = oi; }
    }

    // sum exp(l - max)
    float se = 0.f;
    #pragma unroll
    for (int k = 0; k < 4; k++)
        if (lane + k * 32 < Cc) se += expf(lv[k] - mv);
    #pragma unroll
    for (int o = 16; o > 0; o >>= 1)
        se += __shfl_xor_sync(0xFFFFFFFFu, se, o);

    if (lane == 0) {
        g_s[row]   = 1.f / fmaxf(sqrtf(s2), 1e-8f);
        g_w[row]   = 1.f / se;
        g_cls[row] = mi;
        atomicAdd(&g_cnt[mi], 1.f);
    }
}

// ---------------- transpose + bf16 hi/lo split of y = sqrt(s)*x ----------------
__global__ void k_split(const float* __restrict__ x) {
    __shared__ float sm[32][33];
    int d0 = blockIdx.x * 32, n0 = blockIdx.y * 32;
    int tx = threadIdx.x & 31, ty = threadIdx.x >> 5;   // 32x8
    #pragma unroll
    for (int i = ty; i < 32; i += 8) {
        float sq = sqrtf(g_s[n0 + i]);
        sm[i][tx] = x[(size_t)(n0 + i) * Dd + d0 + tx] * sq;
    }
    __syncthreads();
    #pragma unroll
    for (int r = ty; r < 32; r += 8) {
        float v = sm[tx][r];                        // y[n0+tx][d0+r]
        __nv_bfloat16 hi = __float2bfloat16(v);
        float lo = v - __bfloat162float(hi);
        g_yhi[(size_t)(d0 + r) * Nn + n0 + tx] = hi;
        g_ylo[(size_t)(d0 + r) * Nn + n0 + tx] = __float2bfloat16(lo);
    }
}

// ---------------- G = Y^T Y via WMMA, cp.async 2-stage, 512 threads ----------------
#define KC 64
#define KCHUNKS (Nn / KC)       // 128 chunks, split nonuniformly over SPLITK
#define PITCH 72                // bf16/row: 144B stride = 9*16B (ldmatrix-aligned)
#define TILE_E (128 * PITCH)    // elems per plane
#define STAGE_E (4 * TILE_E)    // Ah,Al,Bh,Bl
#define GRAM_SMEM (2 * STAGE_E * 2)   // 147456 bytes
#define GT 512

__device__ __forceinline__ void fill_plane_async(__nv_bfloat16* sm,
                                                 const __nv_bfloat16* plane,
                                                 int row0, int k0, int tid) {
    #pragma unroll
    for (int p = 0; p < 2; p++) {
        int idx = p * GT + tid;      // 0..1023 : 128 rows x 8 chunks of 16B
        int row = idx >> 3;
        int q   = idx & 7;
        cp16(sm + row * PITCH + q * 8,
             plane + (size_t)(row0 + row) * Nn + k0 + q * 8);
    }
}

__device__ __forceinline__ void fill_stage(__nv_bfloat16* base, int a0, int b0,
                                           bool diag, int k0, int tid) {
    fill_plane_async(base,              g_yhi, a0, k0, tid);
    fill_plane_async(base + TILE_E,     g_ylo, a0, k0, tid);
    if (!diag) {
        fill_plane_async(base + 2 * TILE_E, g_yhi, b0, k0, tid);
        fill_plane_async(base + 3 * TILE_E, g_ylo, b0, k0, tid);
    }
    CP_COMMIT();
}

__global__ void __launch_bounds__(GT) k_gram_wmma() {
    extern __shared__ __nv_bfloat16 smem[];

    int tid = threadIdx.x;
    int wid = tid >> 5;     // 16 warps
    int wm = wid & 3;       // 4 warps in M (32 rows each)
    int wn = wid >> 2;      // 4 warps in N (32 cols each)

    // decode upper-tri tile index (4x4 tiles of 128)
    int t = blockIdx.x, ti = 0, rem = t;
    while (rem >= 4 - ti) { rem -= 4 - ti; ti++; }
    int tj = ti + rem;
    int a0 = ti * 128, b0 = tj * 128;
    bool diag = (ti == tj);

    int split = blockIdx.y;
    int cstart = (split * KCHUNKS) / SPLITK;
    int cend   = ((split + 1) * KCHUNKS) / SPLITK;
    int nst = cend - cstart;

    wmma::fragment<wmma::accumulator, 16, 16, 16, float> acc[2][2];
    #pragma unroll
    for (int i = 0; i < 2; i++)
        #pragma unroll
        for (int j = 0; j < 2; j++)
            wmma::fill_fragment(acc[i][j], 0.f);

    // prefetch stage 0
    fill_stage(smem, a0, b0, diag, cstart * KC, tid);

    for (int st = 0; st < nst; st++) {
        int cur = st & 1;
        if (st + 1 < nst) {
            fill_stage(smem + (1 - cur) * STAGE_E, a0, b0, diag,
                       (cstart + st + 1) * KC, tid);
            CP_WAIT(1);
        } else {
            CP_WAIT(0);
        }
        __syncthreads();

        __nv_bfloat16* Ah = smem + cur * STAGE_E;
        __nv_bfloat16* Al = Ah + TILE_E;
        const __nv_bfloat16* bh = diag ? Ah : (Ah + 2 * TILE_E);
        const __nv_bfloat16* bl = diag ? Al : (Ah + 3 * TILE_E);

        #pragma unroll
        for (int kk = 0; kk < KC / 16; kk++) {
            wmma::fragment<wmma::matrix_a, 16, 16, 16, __nv_bfloat16, wmma::row_major> ah[2], al[2];
            wmma::fragment<wmma::matrix_b, 16, 16, 16, __nv_bfloat16, wmma::col_major> fh[2], fl[2];
            #pragma unroll
            for (int i = 0; i < 2; i++) {
                int r = wm * 32 + i * 16;
                wmma::load_matrix_sync(ah[i], Ah + r * PITCH + kk * 16, PITCH);
                wmma::load_matrix_sync(al[i], Al + r * PITCH + kk * 16, PITCH);
            }
            #pragma unroll
            for (int j = 0; j < 2; j++) {
                int c = wn * 32 + j * 16;
                wmma::load_matrix_sync(fh[j], bh + c * PITCH + kk * 16, PITCH);
                wmma::load_matrix_sync(fl[j], bl + c * PITCH + kk * 16, PITCH);
            }
            #pragma unroll
            for (int i = 0; i < 2; i++)
                #pragma unroll
                for (int j = 0; j < 2; j++) {
                    wmma::mma_sync(acc[i][j], ah[i], fh[j], acc[i][j]);
                    wmma::mma_sync(acc[i][j], ah[i], fl[j], acc[i][j]);
                    wmma::mma_sync(acc[i][j], al[i], fh[j], acc[i][j]);
                }
        }
        __syncthreads();
    }

    float* dst = g_part + ((size_t)split * NTRI2 + blockIdx.x) * 16384;
    #pragma unroll
    for (int i = 0; i < 2; i++)
        #pragma unroll
        for (int j = 0; j < 2; j++)
            wmma::store_matrix_sync(dst + (wm * 32 + i * 16) * 128 + wn * 32 + j * 16,
                                    acc[i][j], 128, wmma::mem_row_major);
}

// ---------------- reduce splits -> G (+ mirror lower triangle) ----------------
__global__ void k_reduce() {
    int tile = blockIdx.y;
    int ti = 0, rem = tile;
    while (rem >= 4 - ti) { rem -= 4 - ti; ti++; }
    int tj = ti + rem;

    int i = blockIdx.x * blockDim.x + threadIdx.x;   // 0..4095 (float4 index)
    int row = i >> 5;
    int c4  = (i & 31) * 4;
    float4 acc = make_float4(0.f, 0.f, 0.f, 0.f);
    #pragma unroll
    for (int s = 0; s < SPLITK; s++) {
        float4 v = *(const float4*)(g_part + ((size_t)s * NTRI2 + tile) * 16384 + row * 128 + c4);
        acc.x += v.x; acc.y += v.y; acc.z += v.z; acc.w += v.w;
    }
    int a = ti * 128 + row, b = tj * 128 + c4;
    *(float4*)(g_G + (size_t)a * Dd + b) = acc;
    if (ti != tj) {
        g_G[(size_t)(b + 0) * Dd + a] = acc.x;
        g_G[(size_t)(b + 1) * Dd + a] = acc.y;
        g_G[(size_t)(b + 2) * Dd + a] = acc.z;
        g_G[(size_t)(b + 3) * Dd + a] = acc.w;
    }
}

// ---------------- per-class weighted sums A, B ----------------
#define RSPLIT 8
__global__ void k_scatter(const float* __restrict__ x) {
    __shared__ float sA[Cc][32];
    __shared__ float sB[Cc][32];
    int c0 = blockIdx.x * 32;
    int r0 = blockIdx.y * (Nn / RSPLIT);
    int tid = threadIdx.x;
    int tx = tid & 31, ty = tid >> 5;

    for (int i = tid; i < Cc * 32; i += 256) { (&sA[0][0])[i] = 0.f; (&sB[0][0])[i] = 0.f; }
    __syncthreads();

    int rend = r0 + (Nn / RSPLIT);
    for (int r = r0 + ty; r < rend; r += 8) {
        int   c  = g_cls[r];
        float w  = g_w[r];
        float ws = w * g_s[r];
        float xv = x[(size_t)r * Dd + c0 + tx];
        atomicAdd(&sA[c][tx], ws * xv);
        atomicAdd(&sB[c][tx], w  * xv);
    }
    __syncthreads();

    for (int i = tid; i < Cc * 32; i += 256) {
        int cl = i >> 5, col = i & 31;
        atomicAdd(&g_A[(size_t)cl * Dd + c0 + col], sA[cl][col]);
        atomicAdd(&g_B[(size_t)cl * Dd + c0 + col], sB[cl][col]);
    }
}

// ---------------- prototypes = (A @ G + B) / counts ----------------
__global__ void k_proto(float* __restrict__ out) {
    int c = blockIdx.x;
    int tid = threadIdx.x;
    __shared__ float sA[Dd];
    for (int i = tid; i < Dd; i += 256) sA[i] = g_A[(size_t)c * Dd + i];
    __syncthreads();

    float acc0 = 0.f, acc1 = 0.f;
    #pragma unroll 8
    for (int k = 0; k < Dd; k++) {
        float a = sA[k];
        acc0 += a * g_G[(size_t)k * Dd + tid];
        acc1 += a * g_G[(size_t)k * Dd + tid + 256];
    }
    float cnt = g_cnt[c];
    float inv = 1.f / fmaxf(cnt, 1.f);
    float p0 = (cnt > 0.f) ? (acc0 + g_B[(size_t)c * Dd + tid])       * inv : 0.f;
    float p1 = (cnt > 0.f) ? (acc1 + g_B[(size_t)c * Dd + tid + 256]) * inv : 0.f;
    out[(size_t)c * Dd + tid]       = p0;
    out[(size_t)c * Dd + tid + 256] = p1;
}

// ---------------- inter_class_matrix[i,j,:] = P[j] - P[i] ----------------
__global__ void k_inter(const float* __restrict__ P, float* __restrict__ out) {
    const int D4 = Dd / 4;
    long total = (long)Cc * Cc * D4;
    long stride = (long)gridDim.x * blockDim.x;
    for (long t = (long)blockIdx.x * blockDim.x + threadIdx.x; t < total; t += stride) {
        int d4 = (int)(t % D4);
        long ij = t / D4;
        int j = (int)(ij % Cc);
        int i = (int)(ij / Cc);
        float4 pj = *(const float4*)(P + (size_t)j * Dd + d4 * 4);
        float4 pi = *(const float4*)(P + (size_t)i * Dd + d4 * 4);
        float4 o;
        o.x = pj.x - pi.x; o.y = pj.y - pi.y;
        o.z = pj.z - pi.z; o.w = pj.w - pi.w;
        ((float4*)out)[t] = o;
    }
}

extern "C" void kernel_launch(void* const* d_in, const int* in_sizes, int n_in,
                              void* d_out, int out_size) {
    const float* x      = (const float*)d_in[0];   // [8192, 512]
    const float* logits = (const float*)d_in[1];   // [8192, 100]
    float* out = (float*)d_out;

    cudaFuncSetAttribute(k_gram_wmma, cudaFuncAttributeMaxDynamicSharedMemorySize, GRAM_SMEM);

    k_zero<<<64, 256>>>();
    k_rowstats<<<Nn / 8, 256>>>(x, logits);
    k_split<<<dim3(Dd / 32, Nn / 32), 256>>>(x);
    k_gram_wmma<<<dim3(NTRI2, SPLITK), GT, GRAM_SMEM>>>();
    k_reduce<<<dim3(16, NTRI2), 256>>>();
    k_scatter<<<dim3(Dd / 32, RSPLIT), 256>>>(x);
    k_proto<<<Cc, 256>>>(out);
    k_inter<<<2560, 256>>>(out, out + (size_t)Cc * Dd);
}

// round 17
// speedup vs baseline: 1.2341x; 1.0382x over previous
#include <cuda_runtime.h>
#include <cuda_bf16.h>
#include <mma.h>
#include <math.h>
#include <stdint.h>

using namespace nvcuda;

#define Nn 8192
#define Dd 512
#define Cc 100

__device__ __forceinline__ uint32_t smem_u32(const void* p) {
    uint32_t a;
    asm("{ .reg .u64 t; cvta.to.shared.u64 t, %1; cvt.u32.u64 %0, t; }" : "=r"(a) : "l"(p));
    return a;
}
__device__ __forceinline__ void cp16(void* sdst, const void* gsrc) {
    uint32_t s = smem_u32(sdst);
    asm volatile("cp.async.cg.shared.global [%0], [%1], 16;" :: "r"(s), "l"(gsrc));
}
#define CP_COMMIT()  asm volatile("cp.async.commit_group;" ::: "memory")
#define CP_WAIT(n)   asm volatile("cp.async.wait_group %0;" :: "n"(n) : "memory")

// ---- scratch (static device memory; no allocations) ----
__device__ float g_s[Nn];
__device__ float g_w[Nn];
__device__ int   g_cls[Nn];
__device__ float g_G[Dd * Dd];
__device__ __nv_bfloat16 g_yhi[Dd * Nn];   // yT hi plane [512][8192]
__device__ __nv_bfloat16 g_ylo[Dd * Nn];   // yT lo plane
#define NTRI2 10
#define SPLITK 14
__device__ float g_part[SPLITK * NTRI2 * 128 * 128];
// scatter partials: fully overwritten each run -> no zeroing needed anywhere
#define RSPLIT 16
__device__ float g_Ap[RSPLIT * Cc * Dd];
__device__ float g_Bp[RSPLIT * Cc * Dd];
__device__ float g_cntp[RSPLIT * Cc];

// ---------------- fused: row stats + transpose + bf16 hi/lo split ----------------
// One block = 32 rows of x (full 512 cols staged in smem; x read ONCE).
#define PREP_SMEM (32 * 129 * 16 + 128)    // float4 sm4[32][129] + ss[32]

__global__ void __launch_bounds__(256) k_prep(const float* __restrict__ x,
                                              const float* __restrict__ logits) {
    extern __shared__ float4 sm4[];                 // [32][129] float4 (= 516 floats pitch)
    float* ss = (float*)(sm4 + 32 * 129);           // sqrt(g_s) per local row
    int n0 = blockIdx.x * 32;
    int lane = threadIdx.x & 31, warp = threadIdx.x >> 5;   // 8 warps

    // stage A: each warp processes 4 rows (load row -> smem, norm, softmax stats)
    #pragma unroll
    for (int i = 0; i < 4; i++) {
        int lr = warp * 4 + i;
        int row = n0 + lr;
        const float4* xr = (const float4*)(x + (size_t)row * Dd);
        float s2 = 0.f;
        #pragma unroll
        for (int k = 0; k < 4; k++) {
            float4 v = xr[lane + k * 32];
            sm4[lr * 129 + lane + k * 32] = v;
            s2 += v.x * v.x + v.y * v.y + v.z * v.z + v.w * v.w;
        }
        #pragma unroll
        for (int o = 16; o > 0; o >>= 1)
            s2 += __shfl_xor_sync(0xFFFFFFFFu, s2, o);

        // logits: max + first-index argmax over 100
        const float* lp = logits + (size_t)row * Cc;
        float lv[4];
        float mv = -3.402823466e38f; int mi = 0x7FFFFFFF;
        #pragma unroll
        for (int k = 0; k < 4; k++) {
            int idx = lane + k * 32;
            lv[k] = (idx < Cc) ? lp[idx] : -3.402823466e38f;
            if (lv[k] > mv) { mv = lv[k]; mi = idx; }
        }
        #pragma unroll
        for (int o = 16; o > 0; o >>= 1) {
            float ov = __shfl_xor_sync(0xFFFFFFFFu, mv, o);
            int   oi = __shfl_xor_sync(0xFFFFFFFFu, mi, o);
            if (ov > mv || (ov == mv && oi < mi)) { mv = ov; mi = oi; }
        }
        float se = 0.f;
        #pragma unroll
        for (int k = 0; k < 4; k++)
            if (lane + k * 32 < Cc) se += expf(lv[k] - mv);
        #pragma unroll
        for (int o = 16; o > 0; o >>= 1)
            se += __shfl_xor_sync(0xFFFFFFFFu, se, o);

        if (lane == 0) {
            float sval = 1.f / fmaxf(sqrtf(s2), 1e-8f);
            g_s[row]   = sval;
            g_w[row]   = 1.f / se;
            g_cls[row] = mi;
            ss[lr]     = sqrtf(sval);
        }
    }
    __syncthreads();

    // stage B: transposed bf16 hi/lo split. lane = local row n, warp strides d.
    const float* smf = (const float*)sm4;           // pitch 516 floats per row
    float sq = ss[lane];
    for (int d = warp; d < Dd; d += 8) {
        float v = smf[lane * 516 + d] * sq;
        __nv_bfloat16 hi = __float2bfloat16(v);
        float lo = v - __bfloat162float(hi);
        g_yhi[(size_t)d * Nn + n0 + lane] = hi;
        g_ylo[(size_t)d * Nn + n0 + lane] = __float2bfloat16(lo);
    }
}

// ---------------- G = Y^T Y via WMMA, cp.async 2-stage (round-6 measured config) --
#define KC 64
#define KCHUNKS (Nn / KC)       // 128 chunks, split nonuniformly over SPLITK
#define PITCH 72                // bf16/row: 144B stride = 9*16B (ldmatrix-aligned)
#define TILE_E (128 * PITCH)    // elems per plane
#define STAGE_E (4 * TILE_E)    // Ah,Al,Bh,Bl
#define GRAM_SMEM (2 * STAGE_E * 2)   // 147456 bytes

__device__ __forceinline__ void fill_plane_async(__nv_bfloat16* sm,
                                                 const __nv_bfloat16* plane,
                                                 int row0, int k0, int tid) {
    #pragma unroll
    for (int p = 0; p < 4; p++) {
        int idx = p * 256 + tid;     // 0..1023 : 128 rows x 8 chunks of 16B
        int row = idx >> 3;
        int q   = idx & 7;
        cp16(sm + row * PITCH + q * 8,
             plane + (size_t)(row0 + row) * Nn + k0 + q * 8);
    }
}

__device__ __forceinline__ void fill_stage(__nv_bfloat16* base, int a0, int b0,
                                           bool diag, int k0, int tid) {
    fill_plane_async(base,              g_yhi, a0, k0, tid);
    fill_plane_async(base + TILE_E,     g_ylo, a0, k0, tid);
    if (!diag) {
        fill_plane_async(base + 2 * TILE_E, g_yhi, b0, k0, tid);
        fill_plane_async(base + 3 * TILE_E, g_ylo, b0, k0, tid);
    }
    CP_COMMIT();
}

__global__ void __launch_bounds__(256) k_gram_wmma() {
    extern __shared__ __nv_bfloat16 smem[];

    int tid = threadIdx.x;
    int wid = tid >> 5;
    int wm = wid & 3;       // 4 warps in M (32 rows each)
    int wn = wid >> 2;      // 2 warps in N (64 cols each)

    int t = blockIdx.x, ti = 0, rem = t;
    while (rem >= 4 - ti) { rem -= 4 - ti; ti++; }
    int tj = ti + rem;
    int a0 = ti * 128, b0 = tj * 128;
    bool diag = (ti == tj);

    int split = blockIdx.y;
    int cstart = (split * KCHUNKS) / SPLITK;
    int cend   = ((split + 1) * KCHUNKS) / SPLITK;
    int nst = cend - cstart;

    wmma::fragment<wmma::accumulator, 16, 16, 16, float> acc[2][4];
    #pragma unroll
    for (int i = 0; i < 2; i++)
        #pragma unroll
        for (int j = 0; j < 4; j++)
            wmma::fill_fragment(acc[i][j], 0.f);

    fill_stage(smem, a0, b0, diag, cstart * KC, tid);

    for (int st = 0; st < nst; st++) {
        int cur = st & 1;
        if (st + 1 < nst) {
            fill_stage(smem + (1 - cur) * STAGE_E, a0, b0, diag,
                       (cstart + st + 1) * KC, tid);
            CP_WAIT(1);
        } else {
            CP_WAIT(0);
        }
        __syncthreads();

        __nv_bfloat16* Ah = smem + cur * STAGE_E;
        __nv_bfloat16* Al = Ah + TILE_E;
        const __nv_bfloat16* bh = diag ? Ah : (Ah + 2 * TILE_E);
        const __nv_bfloat16* bl = diag ? Al : (Ah + 3 * TILE_E);

        #pragma unroll
        for (int kk = 0; kk < KC / 16; kk++) {
            wmma::fragment<wmma::matrix_a, 16, 16, 16, __nv_bfloat16, wmma::row_major> ah[2], al[2];
            wmma::fragment<wmma::matrix_b, 16, 16, 16, __nv_bfloat16, wmma::col_major> fh[4], fl[4];
            #pragma unroll
            for (int i = 0; i < 2; i++) {
                int r = wm * 32 + i * 16;
                wmma::load_matrix_sync(ah[i], Ah + r * PITCH + kk * 16, PITCH);
                wmma::load_matrix_sync(al[i], Al + r * PITCH + kk * 16, PITCH);
            }
            #pragma unroll
            for (int j = 0; j < 4; j++) {
                int c = wn * 64 + j * 16;
                wmma::load_matrix_sync(fh[j], bh + c * PITCH + kk * 16, PITCH);
                wmma::load_matrix_sync(fl[j], bl + c * PITCH + kk * 16, PITCH);
            }
            #pragma unroll
            for (int i = 0; i < 2; i++)
                #pragma unroll
                for (int j = 0; j < 4; j++) {
                    wmma::mma_sync(acc[i][j], ah[i], fh[j], acc[i][j]);
                    wmma::mma_sync(acc[i][j], ah[i], fl[j], acc[i][j]);
                    wmma::mma_sync(acc[i][j], al[i], fh[j], acc[i][j]);
                }
        }
        __syncthreads();
    }

    float* dst = g_part + ((size_t)split * NTRI2 + blockIdx.x) * 16384;
    #pragma unroll
    for (int i = 0; i < 2; i++)
        #pragma unroll
        for (int j = 0; j < 4; j++)
            wmma::store_matrix_sync(dst + (wm * 32 + i * 16) * 128 + wn * 64 + j * 16,
                                    acc[i][j], 128, wmma::mem_row_major);
}

// ---------------- reduce splits -> G (+ mirror lower triangle) ----------------
__global__ void k_reduce() {
    int tile = blockIdx.y;
    int ti = 0, rem = tile;
    while (rem >= 4 - ti) { rem -= 4 - ti; ti++; }
    int tj = ti + rem;

    int i = blockIdx.x * blockDim.x + threadIdx.x;   // 0..4095 (float4 index)
    int row = i >> 5;
    int c4  = (i & 31) * 4;
    float4 acc = make_float4(0.f, 0.f, 0.f, 0.f);
    #pragma unroll
    for (int s = 0; s < SPLITK; s++) {
        float4 v = *(const float4*)(g_part + ((size_t)s * NTRI2 + tile) * 16384 + row * 128 + c4);
        acc.x += v.x; acc.y += v.y; acc.z += v.z; acc.w += v.w;
    }
    int a = ti * 128 + row, b = tj * 128 + c4;
    *(float4*)(g_G + (size_t)a * Dd + b) = acc;
    if (ti != tj) {
        g_G[(size_t)(b + 0) * Dd + a] = acc.x;
        g_G[(size_t)(b + 1) * Dd + a] = acc.y;
        g_G[(size_t)(b + 2) * Dd + a] = acc.z;
        g_G[(size_t)(b + 3) * Dd + a] = acc.w;
    }
}

// ---------------- per-class weighted partials (deterministic, no zero) ----------------
__global__ void k_scatter(const float* __restrict__ x) {
    __shared__ float sA[Cc][32];
    __shared__ float sB[Cc][32];
    __shared__ float sC[Cc];
    int c0 = blockIdx.x * 32;
    int split = blockIdx.y;
    int r0 = split * (Nn / RSPLIT);      // 512 rows per split
    int tid = threadIdx.x;
    int tx = tid & 31, ty = tid >> 5;

    for (int i = tid; i < Cc * 32; i += 256) { (&sA[0][0])[i] = 0.f; (&sB[0][0])[i] = 0.f; }
    for (int i = tid; i < Cc; i += 256) sC[i] = 0.f;
    __syncthreads();

    int rend = r0 + (Nn / RSPLIT);
    for (int r = r0 + ty; r < rend; r += 8) {
        int   c  = g_cls[r];
        float w  = g_w[r];
        float ws = w * g_s[r];
        float xv = x[(size_t)r * Dd + c0 + tx];
        atomicAdd(&sA[c][tx], ws * xv);
        atomicAdd(&sB[c][tx], w  * xv);
        if (blockIdx.x == 0 && tx == 0) atomicAdd(&sC[c], 1.f);
    }
    __syncthreads();

    for (int i = tid; i < Cc * 32; i += 256) {
        int cl = i >> 5, col = i & 31;
        g_Ap[((size_t)split * Cc + cl) * Dd + c0 + col] = sA[cl][col];
        g_Bp[((size_t)split * Cc + cl) * Dd + c0 + col] = sB[cl][col];
    }
    if (blockIdx.x == 0)
        for (int i = tid; i < Cc; i += 256)
            g_cntp[split * Cc + i] = sC[i];
}

// ---------------- prototypes = (A @ G + B) / counts ----------------
__global__ void k_proto(float* __restrict__ out) {
    int c = blockIdx.x;
    int half = blockIdx.y;          // 0 or 1
    int tid = threadIdx.x;          // 256
    int d = half * 256 + tid;
    __shared__ float sA[Dd];

    for (int i = tid; i < Dd; i += 256) {
        float a = 0.f;
        #pragma unroll
        for (int r = 0; r < RSPLIT; r++)
            a += g_Ap[((size_t)r * Cc + c) * Dd + i];
        sA[i] = a;
    }
    __syncthreads();

    float b = 0.f, cnt = 0.f;
    #pragma unroll
    for (int r = 0; r < RSPLIT; r++) {
        b   += g_Bp[((size_t)r * Cc + c) * Dd + d];
        cnt += g_cntp[r * Cc + c];
    }

    float acc = 0.f;
    #pragma unroll 8
    for (int k = 0; k < Dd; k++)
        acc += sA[k] * g_G[(size_t)k * Dd + d];

    float inv = 1.f / fmaxf(cnt, 1.f);
    out[(size_t)c * Dd + d] = (cnt > 0.f) ? (acc + b) * inv : 0.f;
}

// ---------------- inter_class_matrix[i,j,:] = P[j] - P[i] ----------------
__global__ void k_inter(const float* __restrict__ P, float* __restrict__ out) {
    const int D4 = Dd / 4;
    long total = (long)Cc * Cc * D4;
    long stride = (long)gridDim.x * blockDim.x;
    for (long t = (long)blockIdx.x * blockDim.x + threadIdx.x; t < total; t += stride) {
        int d4 = (int)(t % D4);
        long ij = t / D4;
        int j = (int)(ij % Cc);
        int i = (int)(ij / Cc);
        float4 pj = *(const float4*)(P + (size_t)j * Dd + d4 * 4);
        float4 pi = *(const float4*)(P + (size_t)i * Dd + d4 * 4);
        float4 o;
        o.x = pj.x - pi.x; o.y = pj.y - pi.y;
        o.z = pj.z - pi.z; o.w = pj.w - pi.w;
        ((float4*)out)[t] = o;
    }
}

extern "C" void kernel_launch(void* const* d_in, const int* in_sizes, int n_in,
                              void* d_out, int out_size) {
    const float* x      = (const float*)d_in[0];   // [8192, 512]
    const float* logits = (const float*)d_in[1];   // [8192, 100]
    float* out = (float*)d_out;

    cudaFuncSetAttribute(k_prep, cudaFuncAttributeMaxDynamicSharedMemorySize, PREP_SMEM);
    cudaFuncSetAttribute(k_gram_wmma, cudaFuncAttributeMaxDynamicSharedMemorySize, GRAM_SMEM);

    k_prep<<<Nn / 32, 256, PREP_SMEM>>>(x, logits);
    k_gram_wmma<<<dim3(NTRI2, SPLITK), 256, GRAM_SMEM>>>();
    k_reduce<<<dim3(16, NTRI2), 256>>>();
    k_scatter<<<dim3(16, RSPLIT), 256>>>(x);
    k_proto<<<dim3(Cc, 2), 256>>>(out);
    k_inter<<<2560, 256>>>(out, out + (size_t)Cc * Dd);
}